// round 15
// baseline (speedup 1.0000x reference)
#include <cuda_runtime.h>
#include <cuda_bf16.h>
#include <cuda_fp16.h>
#include <math.h>

// Problem constants
#define BATCH 256
#define SEQL  200
#define INF   512
#define HID   256
#define G3    768
#define BL    (BATCH*SEQL)   // 51200

// ---------------- scratch (device globals) -----------------------------------
__device__ float g_xi_f[(size_t)BL * G3];
__device__ float g_xi_r[(size_t)BL * G3];
__device__ float g_seq1[(size_t)BL * 512];
__device__ float g_p[BL];
__device__ __half g_a2[(size_t)BL * 1024];       // A split fp16: [row][hi(512)|lo(512)]
__device__ __half g_w2[2ull * G3 * 1024];        // W split fp16 per dir (hi used)

// ---------------- helpers -----------------------------------------------------
__device__ __forceinline__ unsigned smem_u32(const void* p) {
    unsigned r;
    asm("{ .reg .u64 t; cvta.to.shared.u64 t, %1; cvt.u32.u64 %0, t; }"
        : "=r"(r) : "l"(p));
    return r;
}
__device__ __forceinline__ unsigned mapa_sh(unsigned addr, unsigned rank) {
    unsigned r;
    asm("mapa.shared::cluster.u32 %0, %1, %2;" : "=r"(r) : "r"(addr), "r"(rank));
    return r;
}
__device__ __forceinline__ void st_cluster_u32(unsigned addr, unsigned v) {
    asm volatile("st.shared::cluster.u32 [%0], %1;" :: "r"(addr), "r"(v) : "memory");
}
__device__ __forceinline__ void cluster_arrive() {
    asm volatile("barrier.cluster.arrive.aligned;" ::: "memory");
}
__device__ __forceinline__ void cluster_wait() {
    asm volatile("barrier.cluster.wait.aligned;" ::: "memory");
}
__device__ __forceinline__ void cluster_sync_full() {
    cluster_arrive(); cluster_wait();
}
__device__ __forceinline__ unsigned ctarank() {
    unsigned r;
    asm("mov.u32 %0, %%cluster_ctarank;" : "=r"(r));
    return r;
}
__device__ __forceinline__ float sigmoid_f(float x) {
    return __fdividef(1.f, 1.f + __expf(-x));
}
__device__ __forceinline__ float tanh_f(float x) {
    return 1.f - __fdividef(2.f, __expf(2.f * x) + 1.f);
}
__device__ __forceinline__ void cp_async16(unsigned sdst, const void* gsrc) {
    asm volatile("cp.async.cg.shared.global [%0], [%1], 16;"
                 :: "r"(sdst), "l"(gsrc) : "memory");
}
#define CP_COMMIT()  asm volatile("cp.async.commit_group;" ::: "memory")
#define CP_WAIT(n)   asm volatile("cp.async.wait_group %0;" :: "n"(n) : "memory")
#define SWZ(o) ((o) ^ (((o) >> 3) & 0x70))

__device__ __forceinline__ void ldsm_x4(unsigned* r, unsigned addr) {
    asm volatile("ldmatrix.sync.aligned.m8n8.x4.shared.b16 {%0,%1,%2,%3}, [%4];"
                 : "=r"(r[0]), "=r"(r[1]), "=r"(r[2]), "=r"(r[3]) : "r"(addr));
}
// fp16 MMA (GEMM path)
__device__ __forceinline__ void mma_f16(float* c, const unsigned* a, const unsigned* b) {
    asm volatile("mma.sync.aligned.m16n8k16.row.col.f32.f16.f16.f32 "
                 "{%0,%1,%2,%3}, {%4,%5,%6,%7}, {%8,%9}, {%0,%1,%2,%3};"
                 : "+f"(c[0]), "+f"(c[1]), "+f"(c[2]), "+f"(c[3])
                 : "r"(a[0]), "r"(a[1]), "r"(a[2]), "r"(a[3]),
                   "r"(b[0]), "r"(b[1]));
}
// bf16 MMA (recurrence path)
__device__ __forceinline__ void mma_bf16(float* c, const unsigned* a, const unsigned* b) {
    asm volatile("mma.sync.aligned.m16n8k16.row.col.f32.bf16.bf16.f32 "
                 "{%0,%1,%2,%3}, {%4,%5,%6,%7}, {%8,%9}, {%0,%1,%2,%3};"
                 : "+f"(c[0]), "+f"(c[1]), "+f"(c[2]), "+f"(c[3])
                 : "r"(a[0]), "r"(a[1]), "r"(a[2]), "r"(a[3]),
                   "r"(b[0]), "r"(b[1]));
}
__device__ __forceinline__ unsigned pack_bf16(float a, float b) {
    __nv_bfloat162 t = __floats2bfloat162_rn(a, b);
    return *(unsigned*)&t;
}
__device__ __forceinline__ unsigned pack_f16(float a, float b) {
    __half2 t = __floats2half2_rn(a, b);
    return *(unsigned*)&t;
}

// ---------------- split-fp16 conversion: src[rows,512] -> dst[rows, hi|lo] ----
__global__ __launch_bounds__(256) void convert_split(
    const float* __restrict__ src, __half* __restrict__ dst, int nelem)
{
    const int idx = (blockIdx.x * 256 + threadIdx.x) * 4;
    if (idx >= nelem) return;
    const int row = idx >> 9, col = idx & 511;
    const float4 v = *(const float4*)(src + idx);
    const __half h0 = __float2half_rn(v.x), h1 = __float2half_rn(v.y);
    const __half h2 = __float2half_rn(v.z), h3 = __float2half_rn(v.w);
    const __half l0 = __float2half_rn(v.x - __half2float(h0));
    const __half l1 = __float2half_rn(v.y - __half2float(h1));
    const __half l2 = __float2half_rn(v.z - __half2float(h2));
    const __half l3 = __float2half_rn(v.w - __half2float(h3));
    __half2* dh = (__half2*)(dst + (size_t)row * 1024 + col);
    __half2* dl = (__half2*)(dst + (size_t)row * 1024 + 512 + col);
    dh[0] = __half2(h0, h1); dh[1] = __half2(h2, h3);
    dl[0] = __half2(l0, l1); dl[1] = __half2(l2, l3);
}

// ---------------- HMMA GEMM: xi = A @ W^T + b (fp16 2-term, shared-B chunks) ---
// 8 chunks of k=64; stage = Ah | Al | B (48KB). Warp grid 4m x 2n (warp tile
// 32m x 64n): A-fragment redundancy 2 (was 4), LDSM/warp/kstep 10 -> 8.
#define GST 49152u
#define GT_SMEM (2 * 49152 + 1024)
__global__ __launch_bounds__(256) void gemm_mma(
    const float* __restrict__ bf_, const float* __restrict__ br_)
{
    extern __shared__ char dsm[];
    __shared__ float sbias[128];
    const unsigned sbase = (smem_u32(dsm) + 1023u) & ~1023u;

    const int tid = threadIdx.x;
    const int wid = tid >> 5, lane = tid & 31;
    const int wm = wid >> 1, wn = wid & 1;     // 4 x 2 warp grid
    const int g = lane >> 2, tig = lane & 3;

    const int bx = blockIdx.x;
    const int m_tile = bx / 12;
    const int sub = bx - m_tile * 12;
    const int dir = sub >= 6;
    const int n0 = (dir ? sub - 6 : sub) * 128;
    const int m0 = m_tile * 128;
    float* C = dir ? g_xi_r : g_xi_f;
    const __half* w2 = g_w2 + (size_t)dir * G3 * 1024;
    const float* bias = dir ? br_ : bf_;

    if (tid < 128) sbias[tid] = bias[n0 + tid];

    // A fragment addressing (x4, 16 rows x 16 k); warp covers 32 m (mt<2)
    const int arow = wm * 32 + (lane & 15);
    const unsigned axm = (unsigned)(arow & 7) * 16u;
    const unsigned acol8 = (unsigned)(lane >> 4) * 16u;
    // B fragment addressing (paired x4 covering 16 n x 16 k); warp covers 64 n
    const int brow4 = wn * 64 + (lane & 7) + ((lane >> 4) & 1) * 8;
    const unsigned bxm4 = (unsigned)(lane & 7) * 16u;
    const unsigned bcol4 = (unsigned)((lane >> 3) & 1) * 16u;

    float acc[2][8][4];
#pragma unroll
    for (int mt = 0; mt < 2; mt++)
#pragma unroll
        for (int nt = 0; nt < 8; nt++)
#pragma unroll
            for (int q = 0; q < 4; q++) acc[mt][nt][q] = 0.f;

    const int lrow = tid & 127;
    const int isb = tid >> 7;
    auto load_chunk = [&](int c, int buf) {
        const unsigned stage = sbase + (unsigned)buf * GST;
        const unsigned rowo = (unsigned)lrow * 128u;
        if (isb) {
            const __half* src = w2 + (size_t)(n0 + lrow) * 1024 + c * 64;
#pragma unroll
            for (int q = 0; q < 8; q++)
                cp_async16(stage + 32768u + SWZ(rowo + q * 16u), src + q * 8);
        } else {
            const __half* srch = g_a2 + (size_t)(m0 + lrow) * 1024 + c * 64;
#pragma unroll
            for (int q = 0; q < 8; q++)
                cp_async16(stage + SWZ(rowo + q * 16u), srch + q * 8);
            const __half* srcl = srch + 512;
#pragma unroll
            for (int q = 0; q < 8; q++)
                cp_async16(stage + 16384u + SWZ(rowo + q * 16u), srcl + q * 8);
        }
        CP_COMMIT();
    };

    load_chunk(0, 0);

    for (int c = 0; c < 8; c++) {
        const int buf = c & 1;
        if (c < 7) { load_chunk(c + 1, (c + 1) & 1); CP_WAIT(1); }
        else       { CP_WAIT(0); }
        __syncthreads();

        const unsigned stage = sbase + (unsigned)buf * GST;
        const unsigned ahbuf = stage;
        const unsigned albuf = stage + 16384u;
        const unsigned bbuf  = stage + 32768u;
#pragma unroll
        for (int ks = 0; ks < 4; ks++) {
            const unsigned akc = (unsigned)(ks * 32) + acol8;
            const unsigned bkc = (unsigned)(ks * 32) + bcol4;
            // B fragments once per kstep (shared by hi and lo terms)
            unsigned bfr[4][4];
#pragma unroll
            for (int np = 0; np < 4; np++)
                ldsm_x4(bfr[np],
                        bbuf + (unsigned)(brow4 + np * 16) * 128u + (bkc ^ bxm4));
            // hi term
            unsigned af[2][4];
#pragma unroll
            for (int mt = 0; mt < 2; mt++)
                ldsm_x4(af[mt], ahbuf + (unsigned)(arow + mt * 16) * 128u + (akc ^ axm));
#pragma unroll
            for (int mt = 0; mt < 2; mt++)
#pragma unroll
                for (int np = 0; np < 4; np++) {
                    mma_f16(acc[mt][2 * np + 0], af[mt], &bfr[np][0]);
                    mma_f16(acc[mt][2 * np + 1], af[mt], &bfr[np][2]);
                }
            // lo term (reuse af registers)
#pragma unroll
            for (int mt = 0; mt < 2; mt++)
                ldsm_x4(af[mt], albuf + (unsigned)(arow + mt * 16) * 128u + (akc ^ axm));
#pragma unroll
            for (int mt = 0; mt < 2; mt++)
#pragma unroll
                for (int np = 0; np < 4; np++) {
                    mma_f16(acc[mt][2 * np + 0], af[mt], &bfr[np][0]);
                    mma_f16(acc[mt][2 * np + 1], af[mt], &bfr[np][2]);
                }
        }
        __syncthreads();
    }

#pragma unroll
    for (int mt = 0; mt < 2; mt++) {
        const int m = m0 + wm * 32 + mt * 16 + g;
#pragma unroll
        for (int nt = 0; nt < 8; nt++) {
            const int nloc = wn * 64 + nt * 8 + 2 * tig;
            const float b0 = sbias[nloc], b1 = sbias[nloc + 1];
            float2 v0, v1;
            v0.x = acc[mt][nt][0] + b0; v0.y = acc[mt][nt][1] + b1;
            v1.x = acc[mt][nt][2] + b0; v1.y = acc[mt][nt][3] + b1;
            *(float2*)(C + (size_t)m * G3 + n0 + nloc) = v0;
            *(float2*)(C + (size_t)(m + 8) * G3 + n0 + nloc) = v1;
        }
    }
}

// ---------------- cluster-persistent GRU recurrence ---------------------------
// R11 shell; k-loop reordered: ks2 outer, terms inner -> A fragments loaded
// once per ks2 (Ah serves Wh and Wl terms; Wh serves Ah and Al terms).
// LDSM/warp/ks2: 15 -> 10.
#define RW_HI    0u
#define RW_LO    98304u
#define RA_BASE  196608u      // two buffers of 16KB (hi 8KB + lo 8KB)
#define GRU_SMEM_BYTES 229376u

__global__ void __launch_bounds__(256, 1) __cluster_dims__(4, 1, 1)
gru_cluster(const float* __restrict__ whh_f, const float* __restrict__ whh_r,
            const float* __restrict__ bhh_f, const float* __restrict__ bhh_r,
            int layer)
{
    extern __shared__ char rsm[];
    const unsigned sb = smem_u32(rsm);

    const unsigned rank = ctarank();
    const int cid = blockIdx.x >> 2;
    const int dir = cid >> 4;
    const int bg  = cid & 15;

    const float* xi  = dir ? g_xi_r : g_xi_f;
    const float* whh = dir ? whh_r : whh_f;
    const float* bhh = dir ? bhh_r : bhh_f;
    const int zoff = dir * HID;

    const int tid = threadIdx.x;
    const int w = tid >> 5, lane = tid & 31;

    if (tid < 192) {
        const int n = tid;
        const int gg = n >> 6, hl = n & 63;
        const float* wrow = whh + (size_t)(gg * HID + rank * 64 + hl) * HID;
        const unsigned xm = (unsigned)(n & 7) * 16u;
#pragma unroll 4
        for (int kk = 0; kk < 128; kk++) {
            const float2 v = *(const float2*)(wrow + 2 * kk);
            const float h0f = __bfloat162float(__float2bfloat16(v.x));
            const float h1f = __bfloat162float(__float2bfloat16(v.y));
            const unsigned off = ((unsigned)(kk * 4)) ^ xm;
            *(unsigned*)(rsm + (unsigned)n * 512u + RW_HI + off) = pack_bf16(v.x, v.y);
            *(unsigned*)(rsm + (unsigned)n * 512u + RW_LO + off) =
                pack_bf16(v.x - h0f, v.y - h1f);
        }
    }
    for (unsigned i = tid; i < 8192; i += 256)
        *(unsigned*)(rsm + RA_BASE + i * 4) = 0u;
    __syncthreads();
    cluster_sync_full();

    const int hl2 = w * 8 + (lane & 3) * 2;
    const int hg0 = rank * 64 + hl2;
    const int b0 = lane >> 2;
    const float2 br2 = *(const float2*)(bhh + hg0);
    const float2 bz2 = *(const float2*)(bhh + HID + hg0);
    const float2 bn2 = *(const float2*)(bhh + 2 * HID + hg0);

    const unsigned arow_off = (unsigned)(lane & 15) * 512u;
    const unsigned axor = (unsigned)((lane & 15) & 7) * 16u;
    const unsigned acol = (unsigned)(lane >> 4) * 16u;
    const unsigned bxor = (unsigned)(lane & 7) * 16u;
    const unsigned bcol = (unsigned)(lane >> 3) * 16u;
    unsigned wrow_off[3];
#pragma unroll
    for (int gg = 0; gg < 3; gg++)
        wrow_off[gg] = (unsigned)((gg * 64 + w * 8 + (lane & 7)) * 512);

    const unsigned xw0 = (unsigned)(b0 & 7) * 16u;
    const unsigned xw1 = (unsigned)((b0 + 8) & 7) * 16u;
    const unsigned relH0 = (unsigned)b0 * 512u + (((unsigned)(2 * hg0)) ^ xw0);
    const unsigned relH1 = (unsigned)(b0 + 8) * 512u + (((unsigned)(2 * hg0)) ^ xw1);
    unsigned rmap[4];
#pragma unroll
    for (unsigned r = 0; r < 4; r++) rmap[r] = mapa_sh(sb, r);

    float2 xig[3][2];
    {
        const int t0 = dir ? (SEQL - 1) : 0;
        const float* xp0 = xi + ((size_t)(bg * 16 + b0) * SEQL + t0) * G3 + hg0;
        const float* xp1 = xi + ((size_t)(bg * 16 + b0 + 8) * SEQL + t0) * G3 + hg0;
#pragma unroll
        for (int gg = 0; gg < 3; gg++) {
            xig[gg][0] = *(const float2*)(xp0 + gg * HID);
            xig[gg][1] = *(const float2*)(xp1 + gg * HID);
        }
    }

    for (int s = 0; s < SEQL; s++) {
        const int t = dir ? (SEQL - 1 - s) : s;
        const unsigned rdb = RA_BASE + (unsigned)(s & 1) * 16384u;
        const unsigned wrb = RA_BASE + (unsigned)((s + 1) & 1) * 16384u;

        float acc[3][4];
#pragma unroll
        for (int gg = 0; gg < 3; gg++)
#pragma unroll
            for (int q = 0; q < 4; q++) acc[gg][q] = 0.f;

        const unsigned AbH = sb + rdb;
        const unsigned AbL = AbH + 8192u;
        const unsigned WbH = sb + RW_HI;
        const unsigned WbL = sb + RW_LO;
#pragma unroll
        for (int ks2 = 0; ks2 < 8; ks2++) {
            const unsigned k0b = (unsigned)(ks2 * 64);
            // A fragments once per ks2
            unsigned ah0[4], ah1[4], al0[4], al1[4];
            ldsm_x4(ah0, AbH + arow_off + ((k0b + acol) ^ axor));
            ldsm_x4(ah1, AbH + arow_off + ((k0b + 32u + acol) ^ axor));
            ldsm_x4(al0, AbL + arow_off + ((k0b + acol) ^ axor));
            ldsm_x4(al1, AbL + arow_off + ((k0b + 32u + acol) ^ axor));
            // Wh: serves Ah and Al terms
#pragma unroll
            for (int gg = 0; gg < 3; gg++) {
                unsigned bfr[4];
                ldsm_x4(bfr, WbH + wrow_off[gg] + ((k0b + bcol) ^ bxor));
                mma_bf16(acc[gg], ah0, bfr);
                mma_bf16(acc[gg], ah1, bfr + 2);
                mma_bf16(acc[gg], al0, bfr);
                mma_bf16(acc[gg], al1, bfr + 2);
            }
            // Wl: serves Ah term
#pragma unroll
            for (int gg = 0; gg < 3; gg++) {
                unsigned bfr[4];
                ldsm_x4(bfr, WbL + wrow_off[gg] + ((k0b + bcol) ^ bxor));
                mma_bf16(acc[gg], ah0, bfr);
                mma_bf16(acc[gg], ah1, bfr + 2);
            }
        }

        float hp[2][2];
        {
            const __nv_bfloat162 h0w = *(const __nv_bfloat162*)(rsm + rdb + relH0);
            const __nv_bfloat162 l0w = *(const __nv_bfloat162*)(rsm + rdb + 8192u + relH0);
            const __nv_bfloat162 h1w = *(const __nv_bfloat162*)(rsm + rdb + relH1);
            const __nv_bfloat162 l1w = *(const __nv_bfloat162*)(rsm + rdb + 8192u + relH1);
            hp[0][0] = __bfloat162float(h0w.x) + __bfloat162float(l0w.x);
            hp[0][1] = __bfloat162float(h0w.y) + __bfloat162float(l0w.y);
            hp[1][0] = __bfloat162float(h1w.x) + __bfloat162float(l1w.x);
            hp[1][1] = __bfloat162float(h1w.y) + __bfloat162float(l1w.y);
        }

        float hnew[2][2];
#pragma unroll
        for (int bi = 0; bi < 2; bi++) {
#pragma unroll
            for (int hj = 0; hj < 2; hj++) {
                const int q = bi * 2 + hj;
                const float gr = acc[0][q] + (hj ? br2.y : br2.x);
                const float gz = acc[1][q] + (hj ? bz2.y : bz2.x);
                const float gn = acc[2][q] + (hj ? bn2.y : bn2.x);
                const float xr = hj ? xig[0][bi].y : xig[0][bi].x;
                const float xz = hj ? xig[1][bi].y : xig[1][bi].x;
                const float xn = hj ? xig[2][bi].y : xig[2][bi].x;
                const float rg = sigmoid_f(xr + gr);
                const float zg = sigmoid_f(xz + gz);
                const float ng = tanh_f(xn + rg * gn);
                hnew[bi][hj] = (1.f - zg) * ng + zg * hp[bi][hj];
            }
        }

        unsigned whw[2], wlw[2];
#pragma unroll
        for (int bi = 0; bi < 2; bi++) {
            const float r0 = __bfloat162float(__float2bfloat16(hnew[bi][0]));
            const float r1 = __bfloat162float(__float2bfloat16(hnew[bi][1]));
            whw[bi] = pack_bf16(hnew[bi][0], hnew[bi][1]);
            wlw[bi] = pack_bf16(hnew[bi][0] - r0, hnew[bi][1] - r1);
        }

#pragma unroll
        for (int bi = 0; bi < 2; bi++) {
            const int b = bg * 16 + b0 + bi * 8;
            const size_t row = (size_t)b * SEQL + t;
            if (layer) {
                *(float2*)(g_seq1 + row * 512 + zoff + hg0) =
                    make_float2(hnew[bi][0], hnew[bi][1]);
            } else {
                const float f0 = __half2float(__float2half_rn(hnew[bi][0]));
                const float f1 = __half2float(__float2half_rn(hnew[bi][1]));
                *(unsigned*)&g_a2[row * 1024 + zoff + hg0] =
                    pack_f16(hnew[bi][0], hnew[bi][1]);
                *(unsigned*)&g_a2[row * 1024 + 512 + zoff + hg0] =
                    pack_f16(hnew[bi][0] - f0, hnew[bi][1] - f1);
            }
        }

#pragma unroll
        for (unsigned r = 0; r < 4; r++) {
            st_cluster_u32(rmap[r] + wrb + relH0, whw[0]);
            st_cluster_u32(rmap[r] + wrb + 8192u + relH0, wlw[0]);
            st_cluster_u32(rmap[r] + wrb + relH1, whw[1]);
            st_cluster_u32(rmap[r] + wrb + 8192u + relH1, wlw[1]);
        }

        cluster_arrive();

        if (s + 1 < SEQL) {
            const int tn_ = dir ? (SEQL - 2 - s) : (s + 1);
            const float* xp0 = xi + ((size_t)(bg * 16 + b0) * SEQL + tn_) * G3 + hg0;
            const float* xp1 = xi + ((size_t)(bg * 16 + b0 + 8) * SEQL + tn_) * G3 + hg0;
#pragma unroll
            for (int gg = 0; gg < 3; gg++) {
                xig[gg][0] = *(const float2*)(xp0 + gg * HID);
                xig[gg][1] = *(const float2*)(xp1 + gg * HID);
            }
        }

        cluster_wait();
    }
}

// ---------------- heads: warp-per-row ------------------------------------------
__global__ __launch_bounds__(256) void fc_heads(
    const float* __restrict__ fc1w, const float* __restrict__ fc1b,
    const float* __restrict__ fc2w, const float* __restrict__ fc2b,
    float* __restrict__ y, float* __restrict__ y2)
{
    __shared__ float ws[11 * 512];
    __shared__ float bsh[11];
    const int tid = threadIdx.x;
    for (int i = tid; i < 5120; i += 256) ws[i] = fc2w[i];
    for (int i = tid; i < 512; i += 256) ws[5120 + i] = fc1w[i];
    if (tid < 10) bsh[tid] = fc2b[tid];
    if (tid == 10) bsh[10] = fc1b[0];
    __syncthreads();

    const int wid = tid >> 5, lane = tid & 31;
    const int bt = blockIdx.x * 8 + wid;
    const float4* row = (const float4*)(g_seq1 + (size_t)bt * 512);
    float4 v[4];
#pragma unroll
    for (int q = 0; q < 4; q++) v[q] = row[q * 32 + lane];

#pragma unroll
    for (int j = 0; j < 11; j++) {
        const float4* wj = (const float4*)(ws + j * 512);
        float s = 0.f;
#pragma unroll
        for (int q = 0; q < 4; q++) {
            const float4 wv = wj[q * 32 + lane];
            s += v[q].x * wv.x + v[q].y * wv.y + v[q].z * wv.z + v[q].w * wv.w;
        }
#pragma unroll
        for (int off = 16; off; off >>= 1) s += __shfl_xor_sync(0xffffffffu, s, off);
        if (lane == 0) {
            if (j < 10) y2[(size_t)bt * 10 + j] = s + bsh[j];
            else        y[bt] = s + bsh[10];
        }
    }
}

__global__ __launch_bounds__(256) void softmax_y_kernel(const float* __restrict__ y) {
    const int b = blockIdx.x;
    __shared__ float sh[256];
    const int tid = threadIdx.x;
    float v = (tid < SEQL) ? y[b * SEQL + tid] : -INFINITY;
    sh[tid] = v; __syncthreads();
    for (int s = 128; s; s >>= 1) {
        if (tid < s) sh[tid] = fmaxf(sh[tid], sh[tid + s]);
        __syncthreads();
    }
    const float mx = sh[0]; __syncthreads();
    const float e = (tid < SEQL) ? __expf(v - mx) : 0.f;
    sh[tid] = e; __syncthreads();
    for (int s = 128; s; s >>= 1) {
        if (tid < s) sh[tid] += sh[tid + s];
        __syncthreads();
    }
    const float inv = 1.f / sh[0];
    if (tid < SEQL) g_p[b * SEQL + tid] = e * inv * 0.1f;
}

__global__ __launch_bounds__(256) void softmax_y2_kernel(
    const float* __restrict__ y2, float* __restrict__ y3)
{
    const int b = blockIdx.x;
    const int tid = threadIdx.x;
    __shared__ float sh[256];
    const float* src = y2 + (size_t)b * 2000;
    float mx = -INFINITY;
    for (int i = tid; i < 2000; i += 256) mx = fmaxf(mx, src[i]);
    sh[tid] = mx; __syncthreads();
    for (int s = 128; s; s >>= 1) {
        if (tid < s) sh[tid] = fmaxf(sh[tid], sh[tid + s]);
        __syncthreads();
    }
    mx = sh[0]; __syncthreads();
    float sum = 0.f;
    for (int i = tid; i < 2000; i += 256) sum += __expf(src[i] - mx);
    sh[tid] = sum; __syncthreads();
    for (int s = 128; s; s >>= 1) {
        if (tid < s) sh[tid] += sh[tid + s];
        __syncthreads();
    }
    const float inv = 1.f / sh[0];
    for (int i = tid; i < 2000; i += 256)
        y3[(size_t)b * 2000 + i] = __expf(src[i] - mx) * inv + g_p[b * SEQL + i / 10];
}

// ---------------- driver ------------------------------------------------------
extern "C" void kernel_launch(void* const* d_in, const int* in_sizes, int n_in,
                              void* d_out, int out_size) {
    (void)in_sizes; (void)n_in; (void)out_size;
    const float* x        = (const float*)d_in[0];
    const float* w_ih_l0  = (const float*)d_in[1];
    const float* w_hh_l0  = (const float*)d_in[2];
    const float* b_ih_l0  = (const float*)d_in[3];
    const float* b_hh_l0  = (const float*)d_in[4];
    const float* w_ih_l0r = (const float*)d_in[5];
    const float* w_hh_l0r = (const float*)d_in[6];
    const float* b_ih_l0r = (const float*)d_in[7];
    const float* b_hh_l0r = (const float*)d_in[8];
    const float* w_ih_l1  = (const float*)d_in[9];
    const float* w_hh_l1  = (const float*)d_in[10];
    const float* b_ih_l1  = (const float*)d_in[11];
    const float* b_hh_l1  = (const float*)d_in[12];
    const float* w_ih_l1r = (const float*)d_in[13];
    const float* w_hh_l1r = (const float*)d_in[14];
    const float* b_ih_l1r = (const float*)d_in[15];
    const float* b_hh_l1r = (const float*)d_in[16];
    const float* fc1_w    = (const float*)d_in[17];
    const float* fc1_b    = (const float*)d_in[18];
    const float* fc2_w    = (const float*)d_in[19];
    const float* fc2_b    = (const float*)d_in[20];

    float* y  = (float*)d_out;
    float* y2 = y + BL;
    float* y3 = y2 + BL * 10;

    static int configured = 0;
    if (!configured) {
        cudaFuncSetAttribute(gru_cluster, cudaFuncAttributeMaxDynamicSharedMemorySize,
                             GRU_SMEM_BYTES);
        cudaFuncSetAttribute(gemm_mma, cudaFuncAttributeMaxDynamicSharedMemorySize,
                             GT_SMEM);
        configured = 1;
    }

    __half* a2p = nullptr;
    __half* w2p = nullptr;
    cudaGetSymbolAddress((void**)&a2p, g_a2);
    cudaGetSymbolAddress((void**)&w2p, g_w2);

    const int A_ELEM = BL * 512;
    const int W_ELEM = G3 * 512;

    // ---- layer 0 ----
    convert_split<<<A_ELEM / 1024, 256>>>(x, a2p, A_ELEM);
    convert_split<<<W_ELEM / 1024, 256>>>(w_ih_l0,  w2p,                     W_ELEM);
    convert_split<<<W_ELEM / 1024, 256>>>(w_ih_l0r, w2p + (size_t)G3 * 1024, W_ELEM);
    gemm_mma<<<(BL / 128) * 12, 256, GT_SMEM>>>(b_ih_l0, b_ih_l0r);
    gru_cluster<<<128, 256, GRU_SMEM_BYTES>>>(w_hh_l0, w_hh_l0r, b_hh_l0, b_hh_l0r, 0);
    // layer-0 recurrence wrote split-fp16 g_a2 directly (no convert needed)

    // ---- layer 1 ----
    convert_split<<<W_ELEM / 1024, 256>>>(w_ih_l1,  w2p,                     W_ELEM);
    convert_split<<<W_ELEM / 1024, 256>>>(w_ih_l1r, w2p + (size_t)G3 * 1024, W_ELEM);
    gemm_mma<<<(BL / 128) * 12, 256, GT_SMEM>>>(b_ih_l1, b_ih_l1r);
    gru_cluster<<<128, 256, GRU_SMEM_BYTES>>>(w_hh_l1, w_hh_l1r, b_hh_l1, b_hh_l1r, 1);

    // ---- heads ----
    fc_heads<<<BL / 8, 256>>>(fc1_w, fc1_b, fc2_w, fc2_b, y, y2);
    softmax_y_kernel<<<BATCH, 256>>>(y);
    softmax_y2_kernel<<<BATCH, 256>>>(y2, y3);
}